// round 14
// baseline (speedup 1.0000x reference)
#include <cuda_runtime.h>
#include <cuda_fp16.h>
#include <cstdint>

#define C 32
#define WARPS 8
#define N_VOX_MAX 262144
#define STRIDE 20            // words per staged row (80B): 16B-aligned, conflict-free
#define ROWS_T 32            // pairs per warp-iteration
#define BUF_WORDS (ROWS_T * STRIDE)       // 640 words = 2.5KB
#define WARP_WORDS (2 * BUF_WORDS)        // double buffer
#define SMEM_BYTES (WARPS * WARP_WORDS * 4)  // 40KB
#define WLO_SCALE 2048.0f
#define WLO_INV  (1.0f / 2048.0f)

// fp16 feature cache: 262144 rows x 32 half = 16MB (device scratch; allowed)
__device__ __align__(16) __half g_feat16[N_VOX_MAX * C];

// ---------------------------------------------------------------------------
static __device__ __forceinline__ uint32_t smem_u32(const void* p) {
    uint32_t a;
    asm("{ .reg .u64 t; cvta.to.shared.u64 t, %1; cvt.u32.u64 %0, t; }"
        : "=r"(a) : "l"(p));
    return a;
}

static __device__ __forceinline__ void mma_f16(float* d, const uint32_t* a,
                                               const uint32_t* b) {
    asm volatile(
        "mma.sync.aligned.m16n8k16.row.col.f32.f16.f16.f32 "
        "{%0,%1,%2,%3}, {%4,%5,%6,%7}, {%8,%9}, {%0,%1,%2,%3};"
        : "+f"(d[0]), "+f"(d[1]), "+f"(d[2]), "+f"(d[3])
        : "r"(a[0]), "r"(a[1]), "r"(a[2]), "r"(a[3]), "r"(b[0]), "r"(b[1]));
}

// ---------------------------------------------------------------------------
// Kernel 0: fp32 -> fp16 feature conversion (streaming, ~48MB)
// ---------------------------------------------------------------------------
__global__ void cvt_feat_kernel(const float4* __restrict__ in, int n4) {
    int idx = blockIdx.x * blockDim.x + threadIdx.x;
    if (idx < n4) {
        float4 v = in[idx];
        __half2 h0 = __floats2half2_rn(v.x, v.y);
        __half2 h1 = __floats2half2_rn(v.z, v.w);
        uint2 pk = make_uint2(*(uint32_t*)&h0, *(uint32_t*)&h1);
        ((uint2*)g_feat16)[idx] = pk;
    }
}

// ---------------------------------------------------------------------------
// Kernel 1: initialize output with bias
// ---------------------------------------------------------------------------
__global__ void init_bias_kernel(float* __restrict__ out,
                                 const float* __restrict__ bias, int n4) {
    int idx = blockIdx.x * blockDim.x + threadIdx.x;
    if (idx < n4) {
        const float4* b4 = (const float4*)bias;
        ((float4*)out)[idx] = b4[idx & 7];
    }
}

// ---------------------------------------------------------------------------
// Kernel 2: transposed GEMM, fp16 features (pre-converted) + W-side split.
//   d = (Wh @ a) + (Wls @ a) * (1/2048)
// W is the MMA A operand (M=32 couts, permuted rows); gathered fp16 rows are
// the B operand (N=pairs). Lane accumulators hold 4 consecutive couts per
// pair -> red.global.add.v4 straight from registers.
// ---------------------------------------------------------------------------
__global__ __launch_bounds__(256, 2) void spconv_hmma_kernel(
    const float* __restrict__ weights,
    const int2* __restrict__ nbmap,
    float* __restrict__ out,
    int P, int blocksPerSeg)
{
    extern __shared__ uint32_t S[];

    const int tid  = threadIdx.x;
    const int wid  = tid >> 5;
    const int lane = tid & 31;
    const int l4   = lane >> 2;   // 0..7
    const int lm4  = lane & 3;    // 0..3
    const int c4   = lane & 3;    // 16B chunk within 64B row (gather)
    const int r4   = lane >> 2;   // row-within-group (gather)

    const int seg = blockIdx.x / blocksPerSeg;
    const int blk = blockIdx.x % blocksPerSeg;

    // ---- register-resident W fragments (hi & scaled-lo) as MMA A-operand ----
    // Row->cout permutation: m-tile m, row r<8 -> cout 4r+2m ; r>=8 -> 4(r-8)+2m+1
    const float* W = weights + seg * C * C;   // W[cin][cout]
    uint32_t Wh[2][2][4], Wls[2][2][4];
    #pragma unroll
    for (int m = 0; m < 2; m++) {
        #pragma unroll
        for (int kc = 0; kc < 2; kc++) {
            #pragma unroll
            for (int r = 0; r < 4; r++) {
                int cout = 4 * l4 + 2 * m + (r & 1);
                int kk   = 2 * lm4 + 16 * kc + ((r >> 1) * 8);
                float w0 = W[kk * C + cout];
                float w1 = W[(kk + 1) * C + cout];
                __half2 h = __floats2half2_rn(w0, w1);
                float h0 = __low2float(h), h1 = __high2float(h);
                __half2 l = __floats2half2_rn((w0 - h0) * WLO_SCALE,
                                              (w1 - h1) * WLO_SCALE);
                Wh[m][kc][r]  = *(uint32_t*)&h;
                Wls[m][kc][r] = *(uint32_t*)&l;
            }
        }
    }

    // ---- per-warp contiguous pair range ----
    const int segStart = seg * P;
    const int segEnd   = segStart + P;
    const int warpsPerSeg = blocksPerSeg * WARPS;
    const int perWarp  = (P + warpsPerSeg - 1) / warpsPerSeg;
    const int wStart = segStart + (blk * WARPS + wid) * perWarp;
    const int wEnd   = min(wStart + perWarp, segEnd);
    if (wStart >= wEnd) return;   // no block-wide syncs below; safe

    uint32_t* Swarp = S + wid * WARP_WORDS;
    const uint32_t sbase = smem_u32(Swarp);
    const int nIter = (wEnd - wStart + ROWS_T - 1) / ROWS_T;

    auto loadIJ = [&](int pB) -> int2 {
        int pc = min(pB + lane, segEnd - 1);
        return nbmap[pc];
    };
    // async gather of 32 fp16 rows (64B each): 4 chunks x 16B, 8 rows/pass
    auto gatherIssue = [&](int bi, int2 ij) {
        uint32_t abase = sbase + bi * (BUF_WORDS * 4);
        #pragma unroll
        for (int g = 0; g < 4; g++) {
            int r = 8 * g + r4;
            int x = __shfl_sync(0xffffffffu, ij.x, r);
            const char* src = (const char*)(g_feat16 + (size_t)x * C) + c4 * 16;
            uint32_t dst = abase + (r * STRIDE + c4 * 4) * 4;
            asm volatile("cp.async.cg.shared.global [%0], [%1], 16;"
                         :: "r"(dst), "l"(src) : "memory");
        }
    };

    // ---- prologue: indices 2 ahead, gather 1 ahead ----
    int2 ij_cur = loadIJ(wStart);
    gatherIssue(0, ij_cur);
    asm volatile("cp.async.commit_group;" ::: "memory");
    int2 ij_next = (nIter > 1) ? loadIJ(wStart + ROWS_T) : ij_cur;

    for (int t = 0; t < nIter; t++) {
        const int pBase = wStart + t * ROWS_T;
        const int vc = min(ROWS_T, wEnd - pBase);
        const int cur = t & 1;

        if (t + 1 < nIter) gatherIssue(cur ^ 1, ij_next);
        asm volatile("cp.async.commit_group;" ::: "memory");

        int2 ij_next2 = (t + 2 < nIter) ? loadIJ(pBase + 2 * ROWS_T) : ij_next;

        asm volatile("cp.async.wait_group 1;" ::: "memory");
        __syncwarp();

        const uint32_t* Af = Swarp + cur * BUF_WORDS;

        // ---- per n-tile (8 pairs): B-frag LDS, MMA, direct RED ----
        #pragma unroll
        for (int n = 0; n < 4; n++) {
            // B frag (col-major fp16): col l4 -> row 8n+l4;
            // b0 = halves (2lm4, 2lm4+1) = u32[lm4]; b1 = u32[lm4+4]; kc adds 8.
            const uint32_t* rp = Af + (8 * n + l4) * STRIDE;
            uint32_t g[2][2];
            g[0][0] = rp[lm4];
            g[0][1] = rp[lm4 + 4];
            g[1][0] = rp[lm4 + 8];
            g[1][1] = rp[lm4 + 12];

            float dh0[4] = {0.f, 0.f, 0.f, 0.f};
            float dh1[4] = {0.f, 0.f, 0.f, 0.f};
            float dl0[4] = {0.f, 0.f, 0.f, 0.f};
            float dl1[4] = {0.f, 0.f, 0.f, 0.f};
            #pragma unroll
            for (int kc = 0; kc < 2; kc++) {
                mma_f16(dh0, Wh[0][kc], g[kc]);
                mma_f16(dh1, Wh[1][kc], g[kc]);
                mma_f16(dl0, Wls[0][kc], g[kc]);
                mma_f16(dl1, Wls[1][kc], g[kc]);
            }

            #pragma unroll
            for (int par = 0; par < 2; par++) {
                int p = n * 8 + 2 * lm4 + par;
                int y = __shfl_sync(0xffffffffu, ij_cur.y, p);
                float v0 = fmaf(dl0[par],     WLO_INV, dh0[par]);
                float v1 = fmaf(dl0[2 + par], WLO_INV, dh0[2 + par]);
                float v2 = fmaf(dl1[par],     WLO_INV, dh1[par]);
                float v3 = fmaf(dl1[2 + par], WLO_INV, dh1[2 + par]);
                if (p < vc) {
                    float* op = out + (size_t)y * C + 4 * l4;
                    asm volatile("red.global.add.v4.f32 [%0], {%1,%2,%3,%4};"
                                 :: "l"(op), "f"(v0), "f"(v1), "f"(v2), "f"(v3)
                                 : "memory");
                }
            }
        }

        ij_cur = ij_next;
        ij_next = ij_next2;
    }
}

// ---------------------------------------------------------------------------
// Inputs: 0 in_feature f32 [N_VOX,32], 1 kernel f32 [27,32,32], 2 bias f32[32],
//         3 nbmap i32 [M,2], 4 nbsizes i32 [27]
// ---------------------------------------------------------------------------
extern "C" void kernel_launch(void* const* d_in, const int* in_sizes, int n_in,
                              void* d_out, int out_size) {
    const float* in_feature = (const float*)d_in[0];
    const float* weights    = (const float*)d_in[1];
    const float* bias       = (const float*)d_in[2];
    const int2*  nbmap      = (const int2*)d_in[3];
    float*       out        = (float*)d_out;

    int M  = in_sizes[3] / 2;
    int K3 = in_sizes[1] / (C * C);
    int P  = M / K3;

    // fp32 -> fp16 feature cache (streaming)
    int nf4 = in_sizes[0] / 4;
    cvt_feat_kernel<<<(nf4 + 255) / 256, 256>>>((const float4*)in_feature, nf4);

    // init output with bias
    int n4 = out_size / 4;
    init_bias_kernel<<<(n4 + 255) / 256, 256>>>(out, bias, n4);

    static int smem_set = 0;
    if (!smem_set) {
        cudaFuncSetAttribute(spconv_hmma_kernel,
                             cudaFuncAttributeMaxDynamicSharedMemorySize,
                             SMEM_BYTES);
        smem_set = 1;
    }

    int blocksPerSeg = 32;
    spconv_hmma_kernel<<<K3 * blocksPerSeg, 256, SMEM_BYTES>>>(
        weights, nbmap, out, P, blocksPerSeg);
}

// round 15
// speedup vs baseline: 1.0961x; 1.0961x over previous
#include <cuda_runtime.h>
#include <cuda_fp16.h>
#include <cstdint>

#define C 32
#define WARPS 8
#define N_VOX_MAX 262144
#define STRIDE 20            // words per staged fp16 row (80B): 16B-aligned, conflict-free
#define ROWS_T 32            // pairs per warp-iteration
#define BUF_WORDS (ROWS_T * STRIDE)       // 640 words = 2.5KB
#define WARP_WORDS (2 * BUF_WORDS)        // double buffer
#define SMEM_BYTES (WARPS * WARP_WORDS * 4)  // 40KB
#define WLO_SCALE 2048.0f
#define WLO_INV  (1.0f / 2048.0f)

// device scratch (static; no allocations)
__device__ __align__(16) __half g_feat16[N_VOX_MAX * C];  // fp16 feature cache (16MB)
__device__ __align__(16) __half g_acc[N_VOX_MAX * C];     // f16 output accumulators (16MB)

// ---------------------------------------------------------------------------
static __device__ __forceinline__ uint32_t smem_u32(const void* p) {
    uint32_t a;
    asm("{ .reg .u64 t; cvta.to.shared.u64 t, %1; cvt.u32.u64 %0, t; }"
        : "=r"(a) : "l"(p));
    return a;
}

static __device__ __forceinline__ void mma_f16(float* d, const uint32_t* a,
                                               const uint32_t* b) {
    asm volatile(
        "mma.sync.aligned.m16n8k16.row.col.f32.f16.f16.f32 "
        "{%0,%1,%2,%3}, {%4,%5,%6,%7}, {%8,%9}, {%0,%1,%2,%3};"
        : "+f"(d[0]), "+f"(d[1]), "+f"(d[2]), "+f"(d[3])
        : "r"(a[0]), "r"(a[1]), "r"(a[2]), "r"(a[3]), "r"(b[0]), "r"(b[1]));
}

static __device__ __forceinline__ uint32_t cvt_f16x2(float x, float y) {
    __half2 h = __floats2half2_rn(x, y);
    return *(uint32_t*)&h;
}

// ---------------------------------------------------------------------------
// Kernel 0: fp32 -> fp16 feature conversion + zero the f16 accumulators
// ---------------------------------------------------------------------------
__global__ void prep_kernel(const float4* __restrict__ in, int n4) {
    int idx = blockIdx.x * blockDim.x + threadIdx.x;
    if (idx < n4) {
        float4 v = in[idx];
        uint2 pk = make_uint2(cvt_f16x2(v.x, v.y), cvt_f16x2(v.z, v.w));
        ((uint2*)g_feat16)[idx] = pk;
        ((uint2*)g_acc)[idx] = make_uint2(0u, 0u);
    }
}

// ---------------------------------------------------------------------------
// Kernel 2 (final): out = bias + float(acc)   (8 halves -> 8 floats / thread)
// ---------------------------------------------------------------------------
__global__ void final_kernel(float* __restrict__ out,
                             const float* __restrict__ bias, int n8) {
    int idx = blockIdx.x * blockDim.x + threadIdx.x;
    if (idx < n8) {
        uint4 a = ((const uint4*)g_acc)[idx];
        const float4* b4 = (const float4*)bias;
        float4 b0 = b4[(idx & 3) * 2];
        float4 b1 = b4[(idx & 3) * 2 + 1];
        float2 f0 = __half22float2(*(__half2*)&a.x);
        float2 f1 = __half22float2(*(__half2*)&a.y);
        float2 f2 = __half22float2(*(__half2*)&a.z);
        float2 f3 = __half22float2(*(__half2*)&a.w);
        float4 o0 = make_float4(f0.x + b0.x, f0.y + b0.y, f1.x + b0.z, f1.y + b0.w);
        float4 o1 = make_float4(f2.x + b1.x, f2.y + b1.y, f3.x + b1.z, f3.y + b1.w);
        ((float4*)out)[idx * 2]     = o0;
        ((float4*)out)[idx * 2 + 1] = o1;
    }
}

// ---------------------------------------------------------------------------
// Kernel 1 (main): transposed GEMM, fp16 features + W-side split; scatter via
// red.global.add.noftz.v4.f16x2 (8 couts / lane-op -> 4 lane-ops per pair).
// ---------------------------------------------------------------------------
__global__ __launch_bounds__(256, 2) void spconv_hmma_kernel(
    const float* __restrict__ weights,
    const int2* __restrict__ nbmap,
    int P, int blocksPerSeg)
{
    extern __shared__ uint32_t S[];

    const int tid  = threadIdx.x;
    const int wid  = tid >> 5;
    const int lane = tid & 31;
    const int l4   = lane >> 2;   // 0..7
    const int lm4  = lane & 3;    // 0..3
    const int c4   = lane & 3;    // 16B chunk within 64B row (gather)
    const int r4   = lane >> 2;   // row-within-group (gather)

    const int seg = blockIdx.x / blocksPerSeg;
    const int blk = blockIdx.x % blocksPerSeg;

    // ---- register-resident W fragments (hi & scaled-lo) as MMA A-operand ----
    // Row->cout permutation: m-tile m, row r<8 -> cout 4r+2m ; r>=8 -> 4(r-8)+2m+1
    // => lane's couts {4l4..4l4+3} across (m,reg) — consecutive.
    const float* W = weights + seg * C * C;   // W[cin][cout]
    uint32_t Wh[2][2][4], Wls[2][2][4];
    #pragma unroll
    for (int m = 0; m < 2; m++) {
        #pragma unroll
        for (int kc = 0; kc < 2; kc++) {
            #pragma unroll
            for (int r = 0; r < 4; r++) {
                int cout = 4 * l4 + 2 * m + (r & 1);
                int kk   = 2 * lm4 + 16 * kc + ((r >> 1) * 8);
                float w0 = W[kk * C + cout];
                float w1 = W[(kk + 1) * C + cout];
                __half2 h = __floats2half2_rn(w0, w1);
                float h0 = __low2float(h), h1 = __high2float(h);
                __half2 l = __floats2half2_rn((w0 - h0) * WLO_SCALE,
                                              (w1 - h1) * WLO_SCALE);
                Wh[m][kc][r]  = *(uint32_t*)&h;
                Wls[m][kc][r] = *(uint32_t*)&l;
            }
        }
    }

    // ---- per-warp contiguous pair range ----
    const int segStart = seg * P;
    const int segEnd   = segStart + P;
    const int warpsPerSeg = blocksPerSeg * WARPS;
    const int perWarp  = (P + warpsPerSeg - 1) / warpsPerSeg;
    const int wStart = segStart + (blk * WARPS + wid) * perWarp;
    const int wEnd   = min(wStart + perWarp, segEnd);
    if (wStart >= wEnd) return;   // no block-wide syncs below; safe

    uint32_t* Swarp = S + wid * WARP_WORDS;
    const uint32_t sbase = smem_u32(Swarp);
    const int nIter = (wEnd - wStart + ROWS_T - 1) / ROWS_T;

    auto loadIJ = [&](int pB) -> int2 {
        int pc = min(pB + lane, segEnd - 1);
        return nbmap[pc];
    };
    // async gather of 32 fp16 rows (64B each): 4 chunks x 16B, 8 rows/pass
    auto gatherIssue = [&](int bi, int2 ij) {
        uint32_t abase = sbase + bi * (BUF_WORDS * 4);
        #pragma unroll
        for (int g = 0; g < 4; g++) {
            int r = 8 * g + r4;
            int x = __shfl_sync(0xffffffffu, ij.x, r);
            const char* src = (const char*)(g_feat16 + (size_t)x * C) + c4 * 16;
            uint32_t dst = abase + (r * STRIDE + c4 * 4) * 4;
            asm volatile("cp.async.cg.shared.global [%0], [%1], 16;"
                         :: "r"(dst), "l"(src) : "memory");
        }
    };

    // ---- prologue: indices 2 ahead, gather 1 ahead ----
    int2 ij_cur = loadIJ(wStart);
    gatherIssue(0, ij_cur);
    asm volatile("cp.async.commit_group;" ::: "memory");
    int2 ij_next = (nIter > 1) ? loadIJ(wStart + ROWS_T) : ij_cur;

    const bool evenL4 = (l4 & 1) == 0;
    const int  jq     = l4 >> 1;          // output 16B quad 0..3 (couts 8jq..8jq+7)

    for (int t = 0; t < nIter; t++) {
        const int pBase = wStart + t * ROWS_T;
        const int vc = min(ROWS_T, wEnd - pBase);
        const int cur = t & 1;

        if (t + 1 < nIter) gatherIssue(cur ^ 1, ij_next);
        asm volatile("cp.async.commit_group;" ::: "memory");

        int2 ij_next2 = (t + 2 < nIter) ? loadIJ(pBase + 2 * ROWS_T) : ij_next;

        asm volatile("cp.async.wait_group 1;" ::: "memory");
        __syncwarp();

        const uint32_t* Af = Swarp + cur * BUF_WORDS;

        // ---- per n-tile (8 pairs): B-frag LDS, MMA, packed-f16x2 RED ----
        #pragma unroll
        for (int n = 0; n < 4; n++) {
            const uint32_t* rp = Af + (8 * n + l4) * STRIDE;
            uint32_t g[2][2];
            g[0][0] = rp[lm4];
            g[0][1] = rp[lm4 + 4];
            g[1][0] = rp[lm4 + 8];
            g[1][1] = rp[lm4 + 12];

            float dh0[4] = {0.f, 0.f, 0.f, 0.f};
            float dh1[4] = {0.f, 0.f, 0.f, 0.f};
            float dl0[4] = {0.f, 0.f, 0.f, 0.f};
            float dl1[4] = {0.f, 0.f, 0.f, 0.f};
            #pragma unroll
            for (int kc = 0; kc < 2; kc++) {
                mma_f16(dh0, Wh[0][kc], g[kc]);
                mma_f16(dh1, Wh[1][kc], g[kc]);
                mma_f16(dl0, Wls[0][kc], g[kc]);
                mma_f16(dl1, Wls[1][kc], g[kc]);
            }

            // epilogue: pair p = n*8 + 2*lm4 + par (same p for partner lane l4^1);
            // lane holds couts 4l4..4l4+3 -> pack 2x f16x2, merge partner via
            // shfl.xor 4, even-l4 lanes emit one v4.f16x2 red (8 couts, 16B).
            #pragma unroll
            for (int par = 0; par < 2; par++) {
                int p = n * 8 + 2 * lm4 + par;
                int y = __shfl_sync(0xffffffffu, ij_cur.y, p);
                float v0 = fmaf(dl0[par],     WLO_INV, dh0[par]);
                float v1 = fmaf(dl0[2 + par], WLO_INV, dh0[2 + par]);
                float v2 = fmaf(dl1[par],     WLO_INV, dh1[par]);
                float v3 = fmaf(dl1[2 + par], WLO_INV, dh1[2 + par]);
                uint32_t pk0 = cvt_f16x2(v0, v1);
                uint32_t pk1 = cvt_f16x2(v2, v3);
                uint32_t q0 = __shfl_xor_sync(0xffffffffu, pk0, 4);
                uint32_t q1 = __shfl_xor_sync(0xffffffffu, pk1, 4);
                if (evenL4 && p < vc) {
                    __half* op = g_acc + (size_t)y * C + 8 * jq;
                    asm volatile(
                        "red.global.add.noftz.v4.f16x2 [%0], {%1,%2,%3,%4};"
                        :: "l"(op), "r"(pk0), "r"(pk1), "r"(q0), "r"(q1)
                        : "memory");
                }
            }
        }

        ij_cur = ij_next;
        ij_next = ij_next2;
    }
}

// ---------------------------------------------------------------------------
// Inputs: 0 in_feature f32 [N_VOX,32], 1 kernel f32 [27,32,32], 2 bias f32[32],
//         3 nbmap i32 [M,2], 4 nbsizes i32 [27]
// ---------------------------------------------------------------------------
extern "C" void kernel_launch(void* const* d_in, const int* in_sizes, int n_in,
                              void* d_out, int out_size) {
    const float* in_feature = (const float*)d_in[0];
    const float* weights    = (const float*)d_in[1];
    const float* bias       = (const float*)d_in[2];
    const int2*  nbmap      = (const int2*)d_in[3];
    float*       out        = (float*)d_out;

    int M  = in_sizes[3] / 2;
    int K3 = in_sizes[1] / (C * C);
    int P  = M / K3;

    // feature fp16 conversion + accumulator zeroing
    int nf4 = in_sizes[0] / 4;
    prep_kernel<<<(nf4 + 255) / 256, 256>>>((const float4*)in_feature, nf4);

    static int smem_set = 0;
    if (!smem_set) {
        cudaFuncSetAttribute(spconv_hmma_kernel,
                             cudaFuncAttributeMaxDynamicSharedMemorySize,
                             SMEM_BYTES);
        smem_set = 1;
    }

    int blocksPerSeg = 32;
    spconv_hmma_kernel<<<K3 * blocksPerSeg, 256, SMEM_BYTES>>>(
        weights, nbmap, P, blocksPerSeg);

    // out = bias + float(acc)
    int n8 = out_size / 8;
    final_kernel<<<(n8 + 255) / 256, 256>>>(out, bias, n8);
}